// round 14
// baseline (speedup 1.0000x reference)
#include <cuda_runtime.h>
#include <cuda_bf16.h>
#include <cstdint>

// ---------------------------------------------------------------------------
// Problem constants
// ---------------------------------------------------------------------------
#define BS_    64
#define SEQ_   1024
#define D_     800
#define NSLOT_ 64
#define NLAB_  72
#define NPOOL_ (BS_ * NSLOT_)    // 4096
#define D4_    (D_ / 4)          // 200

// Device scratch (allocation-free rule): split-bf16 W planes only
__device__ __nv_bfloat16 g_Bhi[NLAB_ * D_];   // [72][800] K-major
__device__ __nv_bfloat16 g_Blo[NLAB_ * D_];

__device__ __forceinline__ uint32_t pack_bf2(__nv_bfloat16 a, __nv_bfloat16 b) {
    __nv_bfloat162 t(a, b);
    return *reinterpret_cast<uint32_t*>(&t);
}

// mma.sync m16n8k16 row.col bf16 -> f32 (arch-agnostic PTX, sm_80+)
__device__ __forceinline__ void mma_bf16(float* c, const uint32_t* a,
                                         uint32_t b0, uint32_t b1) {
    asm volatile(
        "mma.sync.aligned.m16n8k16.row.col.f32.bf16.bf16.f32 "
        "{%0,%1,%2,%3}, {%4,%5,%6,%7}, {%8,%9}, {%0,%1,%2,%3};"
        : "+f"(c[0]), "+f"(c[1]), "+f"(c[2]), "+f"(c[3])
        : "r"(a[0]), "r"(a[1]), "r"(a[2]), "r"(a[3]), "r"(b0), "r"(b1));
}

__device__ __forceinline__ uint32_t smem_u32(const void* p) {
    uint32_t a;
    asm("{ .reg .u64 t; cvta.to.shared.u64 t, %1; cvt.u32.u64 %0, t; }"
        : "=r"(a) : "l"(p));
    return a;
}
__device__ __forceinline__ void cp16(uint32_t dst, const void* src) {
    asm volatile("cp.async.cg.shared.global [%0], [%1], 16;"
                 :: "r"(dst), "l"(src));
}
__device__ __forceinline__ void cp_commit() {
    asm volatile("cp.async.commit_group;");
}
template <int N>
__device__ __forceinline__ void cp_wait() {
    asm volatile("cp.async.wait_group %0;" :: "n"(N));
}
// Full-block barrier (all threads participate on both sides of the split).
__device__ __forceinline__ void block_bar() {
    asm volatile("bar.sync 0;" ::: "memory");
}

// ---------------------------------------------------------------------------
// Kernel 1: W (800x72) -> transposed split-bf16 planes [72][800]
// ---------------------------------------------------------------------------
__global__ __launch_bounds__(256) void convw_kernel(const float* __restrict__ W)
{
    int idx = blockIdx.x * 256 + threadIdx.x;
    if (idx >= D_ * NLAB_) return;
    int k = idx / NLAB_;
    int n = idx - k * NLAB_;
    float w = W[idx];
    __nv_bfloat16 h = __float2bfloat16(w);
    g_Bhi[n * D_ + k] = h;
    g_Blo[n * D_ + k] = __float2bfloat16(w - __bfloat162float(h));
}

// ---------------------------------------------------------------------------
// Kernel 2: WARP-SPECIALIZED fused pool + split-bf16 HMMA GEMM + bias.
// R12 structure (BK=160 double-buffer, lockstep bar.sync), with the warp
// budget rebalanced: 28 warps = 6 consumers (MMA) + 22 producers (pooling).
// ---------------------------------------------------------------------------
#define MT_    32
#define BK_    160
#define NCH_   5                        // 800 / 160
#define STR_   336                      // padded row stride (320B data + 16)
#define OFF_AHI_ 0
#define OFF_ALO_ (MT_ * STR_)           // 10752
#define OFF_BHI_ (2 * MT_ * STR_)       // 21504
#define OFF_BLO_ (OFF_BHI_ + NLAB_ * STR_)   // 45696
#define STAGE_   (OFF_BLO_ + NLAB_ * STR_)   // 69888 per stage
#define META_OFF_ (2 * STAGE_)               // 139776
#define SMEM_G_  (META_OFF_ + 512)           // 140288 B
#define NT_      896                    // 28 warps
#define NCONS_   192                    // 6 consumer warps
#define NPROD_   (NT_ - NCONS_)         // 704 producer threads

__global__ __launch_bounds__(NT_, 1) void gemm_kernel(
    const float* __restrict__ hs,
    const int*   __restrict__ begins,
    const int*   __restrict__ lens,
    const float* __restrict__ bias,
    float*       __restrict__ out)
{
    extern __shared__ char smem[];
    const uint32_t sbase = smem_u32(smem);
    const int tid   = threadIdx.x;
    const int wid   = tid >> 5;
    const int mtile = blockIdx.x;
    const int slot0 = mtile * MT_;
    const int batch = slot0 >> 6;       // 32 slots always within one batch

    int*   sBegin = (int*)  (smem + META_OFF_);
    int*   sLen   = (int*)  (smem + META_OFF_ + 128);
    float* sInv   = (float*)(smem + META_OFF_ + 256);

    // ---- meta ----
    if (tid < MT_) {
        const int bg = begins[slot0 + tid];
        const int ln = lens[slot0 + tid];
        sBegin[tid] = bg;
        sLen[tid]   = ln;
        sInv[tid]   = 1.0f / (float)(ln + 1);
    }
    block_bar();                        // #1: meta visible

    if (wid >= 6) {
        // ================= PRODUCERS (22 warps) =================
        const int ptid = tid - NCONS_;  // 0..703
        const float4* __restrict__ hs4 =
            reinterpret_cast<const float4*>(hs) + (size_t)batch * SEQ_ * D4_;
        const char* gBh = (const char*)g_Bhi;
        const char* gBl = (const char*)g_Blo;

        auto fill_chunk = [&](int c) {
            const uint32_t st = sbase + (c & 1) * STAGE_;
            char* Ab = smem + (c & 1) * STAGE_;
            const int gk = c * (BK_ * 2);        // byte offset into K
            const int k4 = c * (BK_ / 4);        // float4 offset within row

            // B planes via cp.async: 2 x 72 rows x 20 x 16B = 2880 units
            for (int u = ptid; u < 2880; u += NPROD_) {
                int plane = (u >= 1440) ? 1 : 0;
                int rem = u - plane * 1440;
                int r = rem / 20, i = rem - r * 20;
                const char* g = (plane ? gBl : gBh) + (size_t)r * (D_ * 2) + gk + i * 16;
                cp16(st + (plane ? OFF_BLO_ : OFF_BHI_) + r * STR_ + i * 16, g);
            }
            cp_commit();

            // A pooling: 32 slots x 40 float4-lanes = 1280 items
            for (int u = ptid; u < MT_ * 40; u += NPROD_) {
                const int s = u / 40;
                const int l = u - s * 40;
                const int len = sLen[s];
                const float inv = sInv[s];
                const float4* row = hs4 + (size_t)sBegin[s] * D4_ + k4 + l;

                float4 v[8];
                v[0] = row[0];
                #pragma unroll
                for (int r = 1; r < 8; ++r) {
                    v[r] = make_float4(0.f, 0.f, 0.f, 0.f);
                    if (r <= len) v[r] = row[(size_t)r * D4_];
                }
                #pragma unroll
                for (int sh = 4; sh >= 1; sh >>= 1)
                    #pragma unroll
                    for (int i = 0; i < sh; ++i) {
                        v[i].x += v[i + sh].x; v[i].y += v[i + sh].y;
                        v[i].z += v[i + sh].z; v[i].w += v[i + sh].w;
                    }

                const float a0 = v[0].x * inv, a1 = v[0].y * inv;
                const float a2 = v[0].z * inv, a3 = v[0].w * inv;
                __nv_bfloat16 h0 = __float2bfloat16(a0), h1 = __float2bfloat16(a1);
                __nv_bfloat16 h2 = __float2bfloat16(a2), h3 = __float2bfloat16(a3);
                __nv_bfloat16 l0 = __float2bfloat16(a0 - __bfloat162float(h0));
                __nv_bfloat16 l1 = __float2bfloat16(a1 - __bfloat162float(h1));
                __nv_bfloat16 l2 = __float2bfloat16(a2 - __bfloat162float(h2));
                __nv_bfloat16 l3 = __float2bfloat16(a3 - __bfloat162float(h3));

                *(uint2*)(Ab + OFF_AHI_ + s * STR_ + l * 8) =
                    make_uint2(pack_bf2(h0, h1), pack_bf2(h2, h3));
                *(uint2*)(Ab + OFF_ALO_ + s * STR_ + l * 8) =
                    make_uint2(pack_bf2(l0, l1), pack_bf2(l2, l3));
            }
            cp_wait<0>();
        };

        fill_chunk(0);
        block_bar();                    // #2: buf0 ready
        for (int c = 0; c < NCH_; ++c) {
            if (c + 1 < NCH_) fill_chunk(c + 1);
            block_bar();                // #3..#7
        }
    } else {
        // ================= CONSUMERS (MMA, 6 warps) =================
        const int lane = tid & 31;
        const int mg   = wid & 1;            // m16 group
        const int ngrp = wid >> 1;           // 0..2 -> n8-tiles ngrp*3..+2
        const int g    = lane >> 2;
        const int t    = lane & 3;

        float acc[3][4];
        #pragma unroll
        for (int j = 0; j < 3; ++j)
            #pragma unroll
            for (int q = 0; q < 4; ++q) acc[j][q] = 0.0f;

        block_bar();                    // #2: wait for buf0

        for (int c = 0; c < NCH_; ++c) {
            const char* sb  = smem + (c & 1) * STAGE_;
            const char* Ahb = sb + OFF_AHI_ + (mg * 16 + g) * STR_ + t * 4;
            const char* Alb = sb + OFF_ALO_ + (mg * 16 + g) * STR_ + t * 4;
            const char* Bb0 = sb + OFF_BHI_ + (ngrp * 24 + g) * STR_ + t * 4;
            const char* Bl0 = sb + OFF_BLO_ + (ngrp * 24 + g) * STR_ + t * 4;

            #pragma unroll
            for (int s = 0; s < BK_ / 16; ++s) {
                const int ko = s * 32;

                uint32_t ah[4], al[4];
                ah[0] = *(const uint32_t*)(Ahb + ko);
                ah[1] = *(const uint32_t*)(Ahb + 8 * STR_ + ko);
                ah[2] = *(const uint32_t*)(Ahb + ko + 16);
                ah[3] = *(const uint32_t*)(Ahb + 8 * STR_ + ko + 16);
                al[0] = *(const uint32_t*)(Alb + ko);
                al[1] = *(const uint32_t*)(Alb + 8 * STR_ + ko);
                al[2] = *(const uint32_t*)(Alb + ko + 16);
                al[3] = *(const uint32_t*)(Alb + 8 * STR_ + ko + 16);

                #pragma unroll
                for (int j = 0; j < 3; ++j) {
                    const char* bh = Bb0 + j * 8 * STR_ + ko;
                    const char* bl = Bl0 + j * 8 * STR_ + ko;
                    uint32_t bh0 = *(const uint32_t*)(bh);
                    uint32_t bh1 = *(const uint32_t*)(bh + 16);
                    uint32_t bl0 = *(const uint32_t*)(bl);
                    uint32_t bl1 = *(const uint32_t*)(bl + 16);
                    mma_bf16(acc[j], ah, bh0, bh1);
                    mma_bf16(acc[j], ah, bl0, bl1);
                    mma_bf16(acc[j], al, bh0, bh1);
                }
            }
            block_bar();                // #3..#7
        }

        // ---- epilogue: bias + final store ----
        #pragma unroll
        for (int j = 0; j < 3; ++j) {
            const int col = (ngrp * 3 + j) * 8 + 2 * t;
            const float2 bv = *reinterpret_cast<const float2*>(bias + col);
            const int row0 = mtile * MT_ + mg * 16 + g;
            *(float2*)(out + (size_t)row0 * NLAB_ + col) =
                make_float2(acc[j][0] + bv.x, acc[j][1] + bv.y);
            *(float2*)(out + (size_t)(row0 + 8) * NLAB_ + col) =
                make_float2(acc[j][2] + bv.x, acc[j][3] + bv.y);
        }
    }
}

// ---------------------------------------------------------------------------
// Launch wrapper
// Inputs: batch_hs f32[64*1024*800], slot_begins i32[4096], slot_lens i32[4096],
// W_clf f32[800*72], b_clf f32[72]. Output: f32[4096*72].
// ---------------------------------------------------------------------------
extern "C" void kernel_launch(void* const* d_in, const int* in_sizes, int n_in,
                              void* d_out, int out_size)
{
    const float* hs     = (const float*)d_in[0];
    const int*   begins = (const int*)  d_in[1];
    const int*   lens   = (const int*)  d_in[2];
    const float* W      = (const float*)d_in[3];
    const float* bias   = (const float*)d_in[4];
    float*       out    = (float*)d_out;

    cudaFuncSetAttribute(gemm_kernel,
                         cudaFuncAttributeMaxDynamicSharedMemorySize,
                         SMEM_G_);

    convw_kernel<<<(D_ * NLAB_ + 255) / 256, 256>>>(W);
    gemm_kernel<<<NPOOL_ / MT_, NT_, SMEM_G_>>>(hs, begins, lens, bias, out);
}

// round 16
// speedup vs baseline: 1.1994x; 1.1994x over previous
#include <cuda_runtime.h>
#include <cuda_bf16.h>
#include <cstdint>

// ---------------------------------------------------------------------------
// Problem constants
// ---------------------------------------------------------------------------
#define BS_    64
#define SEQ_   1024
#define D_     800
#define NSLOT_ 64
#define NLAB_  72
#define NPOOL_ (BS_ * NSLOT_)    // 4096
#define D4_    (D_ / 4)          // 200

// Device scratch (allocation-free rule): split-bf16 W planes only
__device__ __nv_bfloat16 g_Bhi[NLAB_ * D_];   // [72][800] K-major
__device__ __nv_bfloat16 g_Blo[NLAB_ * D_];

__device__ __forceinline__ uint32_t pack_bf2(__nv_bfloat16 a, __nv_bfloat16 b) {
    __nv_bfloat162 t(a, b);
    return *reinterpret_cast<uint32_t*>(&t);
}

// mma.sync m16n8k16 row.col bf16 -> f32 (arch-agnostic PTX, sm_80+)
__device__ __forceinline__ void mma_bf16(float* c, const uint32_t* a,
                                         uint32_t b0, uint32_t b1) {
    asm volatile(
        "mma.sync.aligned.m16n8k16.row.col.f32.bf16.bf16.f32 "
        "{%0,%1,%2,%3}, {%4,%5,%6,%7}, {%8,%9}, {%0,%1,%2,%3};"
        : "+f"(c[0]), "+f"(c[1]), "+f"(c[2]), "+f"(c[3])
        : "r"(a[0]), "r"(a[1]), "r"(a[2]), "r"(a[3]), "r"(b0), "r"(b1));
}

__device__ __forceinline__ uint32_t smem_u32(const void* p) {
    uint32_t a;
    asm("{ .reg .u64 t; cvta.to.shared.u64 t, %1; cvt.u32.u64 %0, t; }"
        : "=r"(a) : "l"(p));
    return a;
}
__device__ __forceinline__ void cp16(uint32_t dst, const void* src) {
    asm volatile("cp.async.cg.shared.global [%0], [%1], 16;"
                 :: "r"(dst), "l"(src));
}
__device__ __forceinline__ void cp_commit() {
    asm volatile("cp.async.commit_group;");
}
template <int N>
__device__ __forceinline__ void cp_wait() {
    asm volatile("cp.async.wait_group %0;" :: "n"(N));
}

// ---------------------------------------------------------------------------
// Kernel 1: W (800x72) -> transposed split-bf16 planes [72][800]
// ---------------------------------------------------------------------------
__global__ __launch_bounds__(256) void convw_kernel(const float* __restrict__ W)
{
    int idx = blockIdx.x * 256 + threadIdx.x;
    if (idx >= D_ * NLAB_) return;
    int k = idx / NLAB_;
    int n = idx - k * NLAB_;
    float w = W[idx];
    __nv_bfloat16 h = __float2bfloat16(w);
    g_Bhi[n * D_ + k] = h;
    g_Blo[n * D_ + k] = __float2bfloat16(w - __bfloat162float(h));
}

// ---------------------------------------------------------------------------
// Kernel 2: fused pool + split-bf16 HMMA GEMM + bias — FULL-ROW pooling.
// Grid = 128 blocks x 32 slots; 576 threads (18 warps). Phases:
//   1. issue cp.async of B chunk 0; pool the ENTIRE A tile (32 x 800) from
//      hs with full 3200B row reads into resident smem bf16 hi/lo planes.
//   2. 5 K-chunks of 160: issue B c+1 (cp.async, double-buffered), wait,
//      MMA chunk c — 18 warps, one m16n8 tile each (2 m-groups x 9 n-tiles).
// R15 bug fixed: B staging now copies the FULL 320B row (20 x 16B units,
// 2880 total), matching BK=160.
// ---------------------------------------------------------------------------
#define MT_     32
#define BK_     160
#define NCH_    5                         // 800 / 160
#define STRA_   1616                      // A row stride bytes (1600 + 16)
#define STRB_   336                       // B row stride bytes (320 + 16)
#define OFF_ALO_  (MT_ * STRA_)           // 51712
#define A_BYTES_  (2 * MT_ * STRA_)       // 103424
#define BSTAGE_   (2 * NLAB_ * STRB_)     // 48384 (hi + lo planes)
#define OFF_BLO_  (NLAB_ * STRB_)         // 24192 within stage
#define OFF_B_    A_BYTES_                // 103424
#define META_OFF_ (OFF_B_ + 2 * BSTAGE_)  // 200192
#define SMEM_G_   (META_OFF_ + 512)       // 200704 B
#define NT_     576                       // 18 warps

__global__ __launch_bounds__(NT_, 1) void gemm_kernel(
    const float* __restrict__ hs,
    const int*   __restrict__ begins,
    const int*   __restrict__ lens,
    const float* __restrict__ bias,
    float*       __restrict__ out)
{
    extern __shared__ char smem[];
    const uint32_t sbase = smem_u32(smem);
    const int tid   = threadIdx.x;
    const int wid   = tid >> 5;
    const int mtile = blockIdx.x;
    const int slot0 = mtile * MT_;
    const int batch = slot0 >> 6;         // 32 slots always within one batch

    int*   sBegin = (int*)  (smem + META_OFF_);
    int*   sLen   = (int*)  (smem + META_OFF_ + 128);
    float* sInv   = (float*)(smem + META_OFF_ + 256);

    // ---- B chunk staging via cp.async (all threads) ----
    const char* gBh = (const char*)g_Bhi;
    const char* gBl = (const char*)g_Blo;
    auto issue_B = [&](int c) {
        const uint32_t st = sbase + OFF_B_ + (c & 1) * BSTAGE_;
        const int gk = c * (BK_ * 2);     // byte offset into K
        // 2 planes x 72 rows x 20 x 16B = 2880 units (full 320B rows)
        for (int u = tid; u < 2880; u += NT_) {
            int plane = (u >= 1440) ? 1 : 0;
            int rem = u - plane * 1440;
            int r = rem / 20, i = rem - r * 20;
            const char* g = (plane ? gBl : gBh) + (size_t)r * (D_ * 2) + gk + i * 16;
            cp16(st + (plane ? OFF_BLO_ : 0) + r * STRB_ + i * 16, g);
        }
        cp_commit();
    };

    // ---- meta ----
    if (tid < MT_) {
        const int bg = begins[slot0 + tid];
        const int ln = lens[slot0 + tid];
        sBegin[tid] = bg;
        sLen[tid]   = ln;
        sInv[tid]   = 1.0f / (float)(ln + 1);
    }
    issue_B(0);
    __syncthreads();                      // meta visible

    // ================= PHASE 1: full-row pooling of the A tile =================
    {
        const float4* __restrict__ hs4 =
            reinterpret_cast<const float4*>(hs) + (size_t)batch * SEQ_ * D4_;
        char* Ab = smem;

        for (int u = tid; u < MT_ * D4_; u += NT_) {   // 6400 items
            const int s = u / D4_;
            const int l = u - s * D4_;                 // float4 lane 0..199
            const int len = sLen[s];
            const float inv = sInv[s];
            const float4* row = hs4 + (size_t)sBegin[s] * D4_ + l;

            float4 v[8];
            v[0] = row[0];
            #pragma unroll
            for (int r = 1; r < 8; ++r) {
                v[r] = make_float4(0.f, 0.f, 0.f, 0.f);
                if (r <= len) v[r] = row[(size_t)r * D4_];
            }
            #pragma unroll
            for (int sh = 4; sh >= 1; sh >>= 1)
                #pragma unroll
                for (int i = 0; i < sh; ++i) {
                    v[i].x += v[i + sh].x; v[i].y += v[i + sh].y;
                    v[i].z += v[i + sh].z; v[i].w += v[i + sh].w;
                }

            const float a0 = v[0].x * inv, a1 = v[0].y * inv;
            const float a2 = v[0].z * inv, a3 = v[0].w * inv;
            __nv_bfloat16 h0 = __float2bfloat16(a0), h1 = __float2bfloat16(a1);
            __nv_bfloat16 h2 = __float2bfloat16(a2), h3 = __float2bfloat16(a3);
            __nv_bfloat16 l0 = __float2bfloat16(a0 - __bfloat162float(h0));
            __nv_bfloat16 l1 = __float2bfloat16(a1 - __bfloat162float(h1));
            __nv_bfloat16 l2 = __float2bfloat16(a2 - __bfloat162float(h2));
            __nv_bfloat16 l3 = __float2bfloat16(a3 - __bfloat162float(h3));

            *(uint2*)(Ab + s * STRA_ + l * 8) =
                make_uint2(pack_bf2(h0, h1), pack_bf2(h2, h3));
            *(uint2*)(Ab + OFF_ALO_ + s * STRA_ + l * 8) =
                make_uint2(pack_bf2(l0, l1), pack_bf2(l2, l3));
        }
    }
    __syncthreads();                      // A tile complete & visible

    // ================= PHASE 2: MMA over 5 B chunks =================
    const int lane = tid & 31;
    const int mg   = (wid < 9) ? 0 : 1;   // m16 group (warps 0-8 / 9-17)
    const int ngrp = (wid < 9) ? wid : wid - 9;   // n8-tile 0..8
    const int g    = lane >> 2;
    const int t    = lane & 3;

    float acc[4] = {0.f, 0.f, 0.f, 0.f};

    const char* Ahb = smem + (mg * 16 + g) * STRA_ + t * 4;
    const char* Alb = smem + OFF_ALO_ + (mg * 16 + g) * STRA_ + t * 4;

    for (int c = 0; c < NCH_; ++c) {
        if (c + 1 < NCH_) { issue_B(c + 1); cp_wait<1>(); }
        else              { cp_wait<0>(); }
        __syncthreads();                  // B chunk c visible to all

        const char* sb  = smem + OFF_B_ + (c & 1) * BSTAGE_;
        const char* Bhb = sb + (ngrp * 8 + g) * STRB_ + t * 4;
        const char* Blb = sb + OFF_BLO_ + (ngrp * 8 + g) * STRB_ + t * 4;
        const int ck = c * (BK_ * 2);     // byte offset into A's K dim

        #pragma unroll
        for (int s = 0; s < BK_ / 16; ++s) {
            const int ko = s * 32;

            uint32_t ah[4], al[4];
            ah[0] = *(const uint32_t*)(Ahb + ck + ko);
            ah[1] = *(const uint32_t*)(Ahb + 8 * STRA_ + ck + ko);
            ah[2] = *(const uint32_t*)(Ahb + ck + ko + 16);
            ah[3] = *(const uint32_t*)(Ahb + 8 * STRA_ + ck + ko + 16);
            al[0] = *(const uint32_t*)(Alb + ck + ko);
            al[1] = *(const uint32_t*)(Alb + 8 * STRA_ + ck + ko);
            al[2] = *(const uint32_t*)(Alb + ck + ko + 16);
            al[3] = *(const uint32_t*)(Alb + 8 * STRA_ + ck + ko + 16);

            uint32_t bh0 = *(const uint32_t*)(Bhb + ko);
            uint32_t bh1 = *(const uint32_t*)(Bhb + ko + 16);
            uint32_t bl0 = *(const uint32_t*)(Blb + ko);
            uint32_t bl1 = *(const uint32_t*)(Blb + ko + 16);

            mma_bf16(acc, ah, bh0, bh1);
            mma_bf16(acc, ah, bl0, bl1);
            mma_bf16(acc, al, bh0, bh1);
        }
        __syncthreads();                  // all reads of stage (c&1) done
    }

    // ---- epilogue: bias + final store ----
    {
        const int col = ngrp * 8 + 2 * t;
        const float2 bv = *reinterpret_cast<const float2*>(bias + col);
        const int row0 = mtile * MT_ + mg * 16 + g;
        *(float2*)(out + (size_t)row0 * NLAB_ + col) =
            make_float2(acc[0] + bv.x, acc[1] + bv.y);
        *(float2*)(out + (size_t)(row0 + 8) * NLAB_ + col) =
            make_float2(acc[2] + bv.x, acc[3] + bv.y);
    }
}

// ---------------------------------------------------------------------------
// Launch wrapper
// Inputs: batch_hs f32[64*1024*800], slot_begins i32[4096], slot_lens i32[4096],
// W_clf f32[800*72], b_clf f32[72]. Output: f32[4096*72].
// ---------------------------------------------------------------------------
extern "C" void kernel_launch(void* const* d_in, const int* in_sizes, int n_in,
                              void* d_out, int out_size)
{
    const float* hs     = (const float*)d_in[0];
    const int*   begins = (const int*)  d_in[1];
    const int*   lens   = (const int*)  d_in[2];
    const float* W      = (const float*)d_in[3];
    const float* bias   = (const float*)d_in[4];
    float*       out    = (float*)d_out;

    cudaFuncSetAttribute(gemm_kernel,
                         cudaFuncAttributeMaxDynamicSharedMemorySize,
                         SMEM_G_);

    convw_kernel<<<(D_ * NLAB_ + 255) / 256, 256>>>(W);
    gemm_kernel<<<NPOOL_ / MT_, NT_, SMEM_G_>>>(hs, begins, lens, bias, out);
}

// round 17
// speedup vs baseline: 1.3293x; 1.1082x over previous
#include <cuda_runtime.h>
#include <cuda_bf16.h>
#include <cstdint>

// ---------------------------------------------------------------------------
// Problem constants
// ---------------------------------------------------------------------------
#define BS_    64
#define SEQ_   1024
#define D_     800
#define NSLOT_ 64
#define NLAB_  72
#define NPOOL_ (BS_ * NSLOT_)    // 4096
#define D4_    (D_ / 4)          // 200

// Device scratch (allocation-free rule): split-bf16 W planes only
__device__ __nv_bfloat16 g_Bhi[NLAB_ * D_];   // [72][800] K-major
__device__ __nv_bfloat16 g_Blo[NLAB_ * D_];

__device__ __forceinline__ uint32_t pack_bf2(__nv_bfloat16 a, __nv_bfloat16 b) {
    __nv_bfloat162 t(a, b);
    return *reinterpret_cast<uint32_t*>(&t);
}

// mma.sync m16n8k16 row.col bf16 -> f32 (arch-agnostic PTX, sm_80+)
__device__ __forceinline__ void mma_bf16(float* c, const uint32_t* a,
                                         uint32_t b0, uint32_t b1) {
    asm volatile(
        "mma.sync.aligned.m16n8k16.row.col.f32.bf16.bf16.f32 "
        "{%0,%1,%2,%3}, {%4,%5,%6,%7}, {%8,%9}, {%0,%1,%2,%3};"
        : "+f"(c[0]), "+f"(c[1]), "+f"(c[2]), "+f"(c[3])
        : "r"(a[0]), "r"(a[1]), "r"(a[2]), "r"(a[3]), "r"(b0), "r"(b1));
}

__device__ __forceinline__ uint32_t smem_u32(const void* p) {
    uint32_t a;
    asm("{ .reg .u64 t; cvta.to.shared.u64 t, %1; cvt.u32.u64 %0, t; }"
        : "=r"(a) : "l"(p));
    return a;
}
__device__ __forceinline__ void cp16(uint32_t dst, const void* src) {
    asm volatile("cp.async.cg.shared.global [%0], [%1], 16;"
                 :: "r"(dst), "l"(src));
}
__device__ __forceinline__ void cp_commit() {
    asm volatile("cp.async.commit_group;");
}
template <int N>
__device__ __forceinline__ void cp_wait() {
    asm volatile("cp.async.wait_group %0;" :: "n"(N));
}
__device__ __forceinline__ void block_bar() {
    asm volatile("bar.sync 0;" ::: "memory");
}

// ---------------------------------------------------------------------------
// Kernel 1: W (800x72) -> transposed split-bf16 planes [72][800]
// ---------------------------------------------------------------------------
__global__ __launch_bounds__(256) void convw_kernel(const float* __restrict__ W)
{
    int idx = blockIdx.x * 256 + threadIdx.x;
    if (idx >= D_ * NLAB_) return;
    int k = idx / NLAB_;
    int n = idx - k * NLAB_;
    float w = W[idx];
    __nv_bfloat16 h = __float2bfloat16(w);
    g_Bhi[n * D_ + k] = h;
    g_Blo[n * D_ + k] = __float2bfloat16(w - __bfloat162float(h));
}

// ---------------------------------------------------------------------------
// Kernel 2: warp-specialized fused pool + split-bf16 HMMA GEMM + bias.
// R12 skeleton with arbiter-aware warp placement:
//   warps  0-19 : producers (640 threads) — pool A; exactly ONE lane-pair
//                 (2 adjacent float4, same slot/rows) per thread per chunk.
//   warps 20-25 : consumers (192 threads) — HIGHEST warp ids so the
//                 hi-wid-first arbiter prioritizes MMA issue; they also
//                 stage B via cp.async (idle slack).
// BK=160 double-buffered, lockstep bar.sync per chunk.
// ---------------------------------------------------------------------------
#define MT_    32
#define BK_    160
#define NCH_   5                        // 800 / 160
#define STR_   336                      // padded row stride (320B data + 16)
#define OFF_AHI_ 0
#define OFF_ALO_ (MT_ * STR_)           // 10752
#define OFF_BHI_ (2 * MT_ * STR_)       // 21504
#define OFF_BLO_ (OFF_BHI_ + NLAB_ * STR_)   // 45696
#define STAGE_   (OFF_BLO_ + NLAB_ * STR_)   // 69888 per stage
#define META_OFF_ (2 * STAGE_)               // 139776
#define SMEM_G_  (META_OFF_ + 512)           // 140288 B
#define NT_      832                    // 26 warps
#define NPROD_   640                    // warps 0-19
#define NCONS_   192                    // warps 20-25

__global__ __launch_bounds__(NT_, 1) void gemm_kernel(
    const float* __restrict__ hs,
    const int*   __restrict__ begins,
    const int*   __restrict__ lens,
    const float* __restrict__ bias,
    float*       __restrict__ out)
{
    extern __shared__ char smem[];
    const uint32_t sbase = smem_u32(smem);
    const int tid   = threadIdx.x;
    const int wid   = tid >> 5;
    const int mtile = blockIdx.x;
    const int slot0 = mtile * MT_;
    const int batch = slot0 >> 6;       // 32 slots always within one batch

    int*   sBegin = (int*)  (smem + META_OFF_);
    int*   sLen   = (int*)  (smem + META_OFF_ + 128);
    float* sInv   = (float*)(smem + META_OFF_ + 256);

    // ---- meta ----
    if (tid < MT_) {
        const int bg = begins[slot0 + tid];
        const int ln = lens[slot0 + tid];
        sBegin[tid] = bg;
        sLen[tid]   = ln;
        sInv[tid]   = 1.0f / (float)(ln + 1);
    }
    block_bar();                        // meta visible

    if (wid < 20) {
        // ================= PRODUCERS (20 warps, 640 threads) =================
        const int ptid = tid;           // 0..639
        const int s    = ptid / 20;     // slot 0..31
        const int lp   = ptid % 20;     // lane-pair 0..19 within chunk
        const int len  = sLen[s];
        const float inv = sInv[s];
        const float4* __restrict__ rowbase =
            reinterpret_cast<const float4*>(hs) + (size_t)batch * SEQ_ * D4_ +
            (size_t)sBegin[s] * D4_ + 2 * lp;

        auto pool_chunk = [&](int c) {
            char* Ab = smem + (c & 1) * STAGE_;
            const float4* row = rowbase + c * (BK_ / 4);

            // 16 independent predicated loads (2 adjacent float4 x 8 rows)
            float4 v0[8], v1[8];
            v0[0] = row[0];
            v1[0] = row[1];
            #pragma unroll
            for (int r = 1; r < 8; ++r) {
                v0[r] = make_float4(0.f, 0.f, 0.f, 0.f);
                v1[r] = make_float4(0.f, 0.f, 0.f, 0.f);
                if (r <= len) {
                    v0[r] = row[(size_t)r * D4_];
                    v1[r] = row[(size_t)r * D4_ + 1];
                }
            }
            // tree sums (independent pairs)
            #pragma unroll
            for (int sh = 4; sh >= 1; sh >>= 1)
                #pragma unroll
                for (int i = 0; i < sh; ++i) {
                    v0[i].x += v0[i + sh].x; v0[i].y += v0[i + sh].y;
                    v0[i].z += v0[i + sh].z; v0[i].w += v0[i + sh].w;
                    v1[i].x += v1[i + sh].x; v1[i].y += v1[i + sh].y;
                    v1[i].z += v1[i + sh].z; v1[i].w += v1[i + sh].w;
                }

            const float a0 = v0[0].x * inv, a1 = v0[0].y * inv;
            const float a2 = v0[0].z * inv, a3 = v0[0].w * inv;
            const float b0 = v1[0].x * inv, b1 = v1[0].y * inv;
            const float b2 = v1[0].z * inv, b3 = v1[0].w * inv;

            __nv_bfloat16 ha0 = __float2bfloat16(a0), ha1 = __float2bfloat16(a1);
            __nv_bfloat16 ha2 = __float2bfloat16(a2), ha3 = __float2bfloat16(a3);
            __nv_bfloat16 hb0 = __float2bfloat16(b0), hb1 = __float2bfloat16(b1);
            __nv_bfloat16 hb2 = __float2bfloat16(b2), hb3 = __float2bfloat16(b3);
            __nv_bfloat16 la0 = __float2bfloat16(a0 - __bfloat162float(ha0));
            __nv_bfloat16 la1 = __float2bfloat16(a1 - __bfloat162float(ha1));
            __nv_bfloat16 la2 = __float2bfloat16(a2 - __bfloat162float(ha2));
            __nv_bfloat16 la3 = __float2bfloat16(a3 - __bfloat162float(ha3));
            __nv_bfloat16 lb0 = __float2bfloat16(b0 - __bfloat162float(hb0));
            __nv_bfloat16 lb1 = __float2bfloat16(b1 - __bfloat162float(hb1));
            __nv_bfloat16 lb2 = __float2bfloat16(b2 - __bfloat162float(hb2));
            __nv_bfloat16 lb3 = __float2bfloat16(b3 - __bfloat162float(hb3));

            // two lanes = 16 contiguous bytes per plane -> STS.128
            uint4 hi = make_uint4(pack_bf2(ha0, ha1), pack_bf2(ha2, ha3),
                                  pack_bf2(hb0, hb1), pack_bf2(hb2, hb3));
            uint4 lo = make_uint4(pack_bf2(la0, la1), pack_bf2(la2, la3),
                                  pack_bf2(lb0, lb1), pack_bf2(lb2, lb3));
            *(uint4*)(Ab + OFF_AHI_ + s * STR_ + lp * 16) = hi;
            *(uint4*)(Ab + OFF_ALO_ + s * STR_ + lp * 16) = lo;
        };

        pool_chunk(0);
        block_bar();                    // buf0 ready (B waited by consumers)
        for (int c = 0; c < NCH_; ++c) {
            if (c + 1 < NCH_) pool_chunk(c + 1);
            block_bar();
        }
    } else {
        // ================= CONSUMERS (6 warps, highest wids) =================
        const int ctid = tid - NPROD_;  // 0..191
        const int cwid = wid - 20;      // 0..5
        const int lane = tid & 31;
        const int mg   = cwid & 1;           // m16 group
        const int ngrp = cwid >> 1;          // 0..2 -> n8-tiles ngrp*3..+2
        const int g    = lane >> 2;
        const int t    = lane & 3;

        const char* gBh = (const char*)g_Bhi;
        const char* gBl = (const char*)g_Blo;
        auto issue_B = [&](int c) {
            const uint32_t st = sbase + (c & 1) * STAGE_;
            const int gk = c * (BK_ * 2);
            // 2 planes x 72 rows x 20 x 16B = 2880 units, 15 per thread
            for (int u = ctid; u < 2880; u += NCONS_) {
                int plane = (u >= 1440) ? 1 : 0;
                int rem = u - plane * 1440;
                int r = rem / 20, i = rem - r * 20;
                const char* gp = (plane ? gBl : gBh) + (size_t)r * (D_ * 2) + gk + i * 16;
                cp16(st + (plane ? OFF_BLO_ : OFF_BHI_) + r * STR_ + i * 16, gp);
            }
            cp_commit();
        };

        float acc[3][4];
        #pragma unroll
        for (int j = 0; j < 3; ++j)
            #pragma unroll
            for (int q = 0; q < 4; ++q) acc[j][q] = 0.0f;

        issue_B(0);
        cp_wait<0>();
        block_bar();                    // buf0 ready (A pooled by producers)

        for (int c = 0; c < NCH_; ++c) {
            if (c + 1 < NCH_) issue_B(c + 1);

            const char* sb  = smem + (c & 1) * STAGE_;
            const char* Ahb = sb + OFF_AHI_ + (mg * 16 + g) * STR_ + t * 4;
            const char* Alb = sb + OFF_ALO_ + (mg * 16 + g) * STR_ + t * 4;
            const char* Bb0 = sb + OFF_BHI_ + (ngrp * 24 + g) * STR_ + t * 4;
            const char* Bl0 = sb + OFF_BLO_ + (ngrp * 24 + g) * STR_ + t * 4;

            #pragma unroll
            for (int s = 0; s < BK_ / 16; ++s) {
                const int ko = s * 32;

                uint32_t ah[4], al[4];
                ah[0] = *(const uint32_t*)(Ahb + ko);
                ah[1] = *(const uint32_t*)(Ahb + 8 * STR_ + ko);
                ah[2] = *(const uint32_t*)(Ahb + ko + 16);
                ah[3] = *(const uint32_t*)(Ahb + 8 * STR_ + ko + 16);
                al[0] = *(const uint32_t*)(Alb + ko);
                al[1] = *(const uint32_t*)(Alb + 8 * STR_ + ko);
                al[2] = *(const uint32_t*)(Alb + ko + 16);
                al[3] = *(const uint32_t*)(Alb + 8 * STR_ + ko + 16);

                #pragma unroll
                for (int j = 0; j < 3; ++j) {
                    const char* bh = Bb0 + j * 8 * STR_ + ko;
                    const char* bl = Bl0 + j * 8 * STR_ + ko;
                    uint32_t bh0 = *(const uint32_t*)(bh);
                    uint32_t bh1 = *(const uint32_t*)(bh + 16);
                    uint32_t bl0 = *(const uint32_t*)(bl);
                    uint32_t bl1 = *(const uint32_t*)(bl + 16);
                    mma_bf16(acc[j], ah, bh0, bh1);
                    mma_bf16(acc[j], ah, bl0, bl1);
                    mma_bf16(acc[j], al, bh0, bh1);
                }
            }
            cp_wait<0>();               // B chunk c+1 landed (this thread's)
            block_bar();
        }

        // ---- epilogue: bias + final store ----
        #pragma unroll
        for (int j = 0; j < 3; ++j) {
            const int col = (ngrp * 3 + j) * 8 + 2 * t;
            const float2 bv = *reinterpret_cast<const float2*>(bias + col);
            const int row0 = mtile * MT_ + mg * 16 + g;
            *(float2*)(out + (size_t)row0 * NLAB_ + col) =
                make_float2(acc[j][0] + bv.x, acc[j][1] + bv.y);
            *(float2*)(out + (size_t)(row0 + 8) * NLAB_ + col) =
                make_float2(acc[j][2] + bv.x, acc[j][3] + bv.y);
        }
    }
}

// ---------------------------------------------------------------------------
// Launch wrapper
// Inputs: batch_hs f32[64*1024*800], slot_begins i32[4096], slot_lens i32[4096],
// W_clf f32[800*72], b_clf f32[72]. Output: f32[4096*72].
// ---------------------------------------------------------------------------
extern "C" void kernel_launch(void* const* d_in, const int* in_sizes, int n_in,
                              void* d_out, int out_size)
{
    const float* hs     = (const float*)d_in[0];
    const int*   begins = (const int*)  d_in[1];
    const int*   lens   = (const int*)  d_in[2];
    const float* W      = (const float*)d_in[3];
    const float* bias   = (const float*)d_in[4];
    float*       out    = (float*)d_out;

    cudaFuncSetAttribute(gemm_kernel,
                         cudaFuncAttributeMaxDynamicSharedMemorySize,
                         SMEM_G_);

    convw_kernel<<<(D_ * NLAB_ + 255) / 256, 256>>>(W);
    gemm_kernel<<<NPOOL_ / MT_, NT_, SMEM_G_>>>(hs, begins, lens, bias, out);
}